// round 1
// baseline (speedup 1.0000x reference)
#include <cuda_runtime.h>
#include <cstdint>
#include <math.h>

// ---------------- problem constants ----------------
#define B_    2048
#define POOL  512
#define TOPK  4
#define EPL   8
#define GPL   8
#define EMB   768
#define KEYD  768

// output offsets (float32 elements)
#define PK_ROWS   20            // TOPK*(EPL/2) + GPL/2 = 16 + 4
#define PK_OFF    0
#define PK_SZ     ((size_t)B_ * PK_ROWS * EMB)          // 31,457,280
#define PV_OFF    (PK_OFF + PK_SZ)
#define LOSS_OFF  (PV_OFF + PK_SZ)                      // 62,914,560
#define CNT_OFF   (LOSS_OFF + 1)
#define XB_OFF    (CNT_OFF + POOL)

// ---------------- device scratch (no runtime alloc allowed) ----------------
__device__ float g_qn[B_ * KEYD];        // normalized query   (6.3 MB)
__device__ float g_nK[POOL * KEYD];      // normalized keys    (1.5 MB)
__device__ float g_C[B_ * POOL];         // cos_sim            (4 MB)
__device__ float g_partial[16 * POOL];   // column-sum partials
__device__ int   g_idx[B_ * TOPK];
__device__ int   g_cnt[POOL];

// ---------------- kernels ----------------

__global__ void zero_cnt_kernel() {
    g_cnt[threadIdx.x] = 0;
}

// Row-wise L2 normalize (matches F.normalize: x / max(||x||, 1e-12))
__global__ __launch_bounds__(256) void norm_rows_kernel(const float* __restrict__ src,
                                                        float* __restrict__ dst) {
    int row = blockIdx.x;
    const float* s = src + (size_t)row * KEYD;
    float ss = 0.f;
    for (int j = threadIdx.x; j < KEYD; j += 256) {
        float v = s[j];
        ss += v * v;
    }
    #pragma unroll
    for (int off = 16; off; off >>= 1)
        ss += __shfl_xor_sync(0xffffffffu, ss, off);

    __shared__ float sm[8];
    if ((threadIdx.x & 31) == 0) sm[threadIdx.x >> 5] = ss;
    __syncthreads();
    float tot = (threadIdx.x < 8) ? sm[threadIdx.x] : 0.f;
    if (threadIdx.x < 32) {
        #pragma unroll
        for (int off = 4; off; off >>= 1)
            tot += __shfl_xor_sync(0xffffffffu, tot, off);
    }
    __shared__ float inv;
    if (threadIdx.x == 0) inv = 1.0f / fmaxf(sqrtf(tot), 1e-12f);
    __syncthreads();
    float* d = dst + (size_t)row * KEYD;
    float iv = inv;
    for (int j = threadIdx.x; j < KEYD; j += 256) d[j] = s[j] * iv;
}

// fp32 SGEMM: C[B_,POOL] = qn[B_,KEYD] * nK[POOL,KEYD]^T
// BM=128, BN=64, BK=16; 256 threads, 8x4 per-thread micro-tile
#define BM 128
#define BN 64
#define BK 16
#define TM 8
#define TN 4
__global__ __launch_bounds__(256) void gemm_kernel(const float* __restrict__ A,
                                                   const float* __restrict__ Bm,
                                                   float* __restrict__ C) {
    __shared__ float As[BK][BM];
    __shared__ float Bs[BK][BN];
    const int t  = threadIdx.x;
    const int tx = t & 15;     // 0..15  -> N
    const int ty = t >> 4;     // 0..15  -> M
    const int m0 = blockIdx.y * BM;
    const int n0 = blockIdx.x * BN;

    float acc[TM][TN];
    #pragma unroll
    for (int i = 0; i < TM; i++)
        #pragma unroll
        for (int j = 0; j < TN; j++) acc[i][j] = 0.f;

    for (int k0 = 0; k0 < KEYD; k0 += BK) {
        // load A tile (128x16) transposed into As[BK][BM] : 512 float4, 2 per thread
        #pragma unroll
        for (int i = 0; i < 2; i++) {
            int id = t + i * 256;
            int r  = id >> 2;
            int c4 = (id & 3) * 4;
            float4 v = *(const float4*)(A + (size_t)(m0 + r) * KEYD + k0 + c4);
            As[c4 + 0][r] = v.x; As[c4 + 1][r] = v.y;
            As[c4 + 2][r] = v.z; As[c4 + 3][r] = v.w;
        }
        // load B tile (64x16) transposed into Bs[BK][BN] : 256 float4, 1 per thread
        {
            int r  = t >> 2;
            int c4 = (t & 3) * 4;
            float4 v = *(const float4*)(Bm + (size_t)(n0 + r) * KEYD + k0 + c4);
            Bs[c4 + 0][r] = v.x; Bs[c4 + 1][r] = v.y;
            Bs[c4 + 2][r] = v.z; Bs[c4 + 3][r] = v.w;
        }
        __syncthreads();
        #pragma unroll
        for (int kk = 0; kk < BK; kk++) {
            float a[TM], b[TN];
            #pragma unroll
            for (int i = 0; i < TM; i++) a[i] = As[kk][ty * TM + i];
            #pragma unroll
            for (int j = 0; j < TN; j++) b[j] = Bs[kk][tx * TN + j];
            #pragma unroll
            for (int i = 0; i < TM; i++)
                #pragma unroll
                for (int j = 0; j < TN; j++)
                    acc[i][j] = fmaf(a[i], b[j], acc[i][j]);
        }
        __syncthreads();
    }
    #pragma unroll
    for (int i = 0; i < TM; i++)
        #pragma unroll
        for (int j = 0; j < TN; j++)
            C[(size_t)(m0 + ty * TM + i) * POOL + n0 + tx * TN + j] = acc[i][j];
}

// warp-per-row top-4 by smallest distance (1 - cos), ties -> lowest index,
// matching jax.lax.top_k(-distance) stability. Also accumulates counts.
__global__ __launch_bounds__(256) void topk_kernel(const float* __restrict__ C) {
    int row  = (blockIdx.x * blockDim.x + threadIdx.x) >> 5;
    int lane = threadIdx.x & 31;
    if (row >= B_) return;
    const float* crow = C + (size_t)row * POOL;
    float d[16];
    #pragma unroll
    for (int u = 0; u < 16; u++) d[u] = 1.0f - crow[u * 32 + lane];

    #pragma unroll
    for (int k = 0; k < TOPK; k++) {
        float best = INFINITY;
        int   bi   = 0x7fffffff;
        #pragma unroll
        for (int u = 0; u < 16; u++) {
            int p = u * 32 + lane;
            if (d[u] < best || (d[u] == best && p < bi)) { best = d[u]; bi = p; }
        }
        #pragma unroll
        for (int off = 16; off; off >>= 1) {
            float ov = __shfl_xor_sync(0xffffffffu, best, off);
            int   oi = __shfl_xor_sync(0xffffffffu, bi, off);
            if (ov < best || (ov == best && oi < bi)) { best = ov; bi = oi; }
        }
        if (lane == 0) {
            g_idx[row * TOPK + k] = bi;
            atomicAdd(&g_cnt[bi], 1);
        }
        if ((bi & 31) == lane) d[bi >> 5] = INFINITY;  // exclude for next pass
    }
}

// column-sum partials of C: grid (2, 16), 256 threads. partial[gy][col]
__global__ __launch_bounds__(256) void colpart_kernel(const float* __restrict__ C) {
    int col = blockIdx.x * 256 + threadIdx.x;
    int r0  = blockIdx.y * 128;
    float s = 0.f;
    #pragma unroll 4
    for (int r = 0; r < 128; r++) s += C[(size_t)(r0 + r) * POOL + col];
    g_partial[blockIdx.y * POOL + col] = s;
}

// final reduction: loss = 1 - sum_p colsum[p]*cnt[p] / (B*B*K); also writes counts
__global__ __launch_bounds__(512) void finish_kernel(float* __restrict__ out_loss,
                                                     float* __restrict__ out_counts) {
    int p = threadIdx.x;
    float colc = 0.f;
    #pragma unroll
    for (int g = 0; g < 16; g++) colc += g_partial[g * POOL + p];
    int c = g_cnt[p];
    out_counts[p] = (float)c;
    __shared__ float sm[512];
    sm[p] = colc * (float)c;
    __syncthreads();
    for (int s = 256; s > 0; s >>= 1) {
        if (p < s) sm[p] += sm[p + s];
        __syncthreads();
    }
    if (p == 0)
        *out_loss = 1.0f - sm[0] / ((float)B_ * (float)B_ * (float)TOPK);
}

// gather/concat: Pk/Pv.  grid (20, 2048), 192 threads (float4 per thread = 768 floats)
__global__ __launch_bounds__(192) void gather_kernel(const float* __restrict__ e_p,
                                                     const float* __restrict__ g_p,
                                                     float* __restrict__ outPk,
                                                     float* __restrict__ outPv) {
    int b = blockIdx.y;
    int r = blockIdx.x;            // 0..19
    const float *sk, *sv;
    if (r < 16) {
        int p  = g_idx[b * TOPK + (r >> 2)];
        int rr = r & 3;
        sk = e_p + ((size_t)p * EPL + rr) * EMB;
        sv = e_p + ((size_t)p * EPL + 4 + rr) * EMB;
    } else {
        sk = g_p + (size_t)(r - 16) * EMB;
        sv = g_p + (size_t)(r - 16 + 4) * EMB;
    }
    size_t o = ((size_t)b * PK_ROWS + r) * EMB;
    int t = threadIdx.x;
    float4 vk = ((const float4*)sk)[t];
    float4 vv = ((const float4*)sv)[t];
    ((float4*)(outPk + o))[t] = vk;
    ((float4*)(outPv + o))[t] = vv;
}

// ---------------- launch ----------------
extern "C" void kernel_launch(void* const* d_in, const int* in_sizes, int n_in,
                              void* d_out, int out_size) {
    const float* x_querry = (const float*)d_in[0];   // [2048, 768]
    const float* x_block  = (const float*)d_in[1];   // [2048, 768]
    const float* e_k      = (const float*)d_in[2];   // [512, 768]
    const float* e_p      = (const float*)d_in[3];   // [512, 8, 768]
    const float* g_p      = (const float*)d_in[4];   // [8, 768]
    // d_in[5] = l (unused, always 0)
    (void)in_sizes; (void)n_in; (void)out_size;

    float* out = (float*)d_out;

    float* d_qn = nullptr, * d_nK = nullptr, * d_C = nullptr;
    cudaGetSymbolAddress((void**)&d_qn, g_qn);
    cudaGetSymbolAddress((void**)&d_nK, g_nK);
    cudaGetSymbolAddress((void**)&d_C,  g_C);

    zero_cnt_kernel<<<1, POOL>>>();
    norm_rows_kernel<<<POOL, 256>>>(e_k, d_nK);
    norm_rows_kernel<<<B_,  256>>>(x_querry, d_qn);
    gemm_kernel<<<dim3(POOL / BN, B_ / BM), 256>>>(d_qn, d_nK, d_C);
    topk_kernel<<<B_ / 8, 256>>>(d_C);
    colpart_kernel<<<dim3(2, 16), 256>>>(d_C);
    finish_kernel<<<1, 512>>>(out + LOSS_OFF, out + CNT_OFF);
    gather_kernel<<<dim3(PK_ROWS, B_), 192>>>(e_p, g_p, out + PK_OFF, out + PV_OFF);
    cudaMemcpyAsync(out + XB_OFF, x_block, (size_t)B_ * EMB * sizeof(float),
                    cudaMemcpyDeviceToDevice, 0);
}

// round 2
// speedup vs baseline: 1.2661x; 1.2661x over previous
#include <cuda_runtime.h>
#include <cstdint>
#include <math.h>

// ---------------- problem constants ----------------
#define B_    2048
#define POOL  512
#define TOPK  4
#define TOP8  8
#define EPL   8
#define GPL   8
#define EMB   768
#define KEYD  768

// output offsets (float32 elements)
#define PK_ROWS   20            // TOPK*(EPL/2) + GPL/2 = 16 + 4
#define PK_SZ     ((size_t)B_ * PK_ROWS * EMB)
#define PV_OFF    (PK_SZ)
#define LOSS_OFF  (2 * PK_SZ)
#define CNT_OFF   (LOSS_OFF + 1)
#define XB_OFF    (CNT_OFF + POOL)

// ---------------- device scratch ----------------
__device__ float g_C[B_ * POOL];         // cos_sim (tf32-accurate)  4 MB
__device__ float g_invq[B_];
__device__ float g_invk[POOL];
__device__ float g_partial[16 * POOL];
__device__ int   g_idx[B_ * TOPK];
__device__ int   g_cnt[POOL];

// ---------------- helpers ----------------
__device__ __forceinline__ uint32_t f2tf(float f) {
    uint32_t r;
    asm("cvt.rna.tf32.f32 %0, %1;" : "=r"(r) : "f"(f));
    return r;
}

__device__ __forceinline__ void mma_tf32(float* c, const uint32_t* a, const uint32_t* b) {
    asm volatile(
        "mma.sync.aligned.m16n8k8.row.col.f32.tf32.tf32.f32 "
        "{%0,%1,%2,%3}, {%4,%5,%6,%7}, {%8,%9}, {%0,%1,%2,%3};"
        : "+f"(c[0]), "+f"(c[1]), "+f"(c[2]), "+f"(c[3])
        : "r"(a[0]), "r"(a[1]), "r"(a[2]), "r"(a[3]), "r"(b[0]), "r"(b[1]));
}

// ---------------- kernels ----------------

__global__ void zero_cnt_kernel() { g_cnt[threadIdx.x] = 0; }

// inverse L2 norms for x_querry rows (0..B_-1) and e_k rows (B_..B_+POOL-1)
__global__ __launch_bounds__(256) void invnorm_kernel(const float* __restrict__ xq,
                                                      const float* __restrict__ ek) {
    int warp = (blockIdx.x * 256 + threadIdx.x) >> 5;
    int lane = threadIdx.x & 31;
    if (warp >= B_ + POOL) return;
    const float4* s4 = (warp < B_)
        ? (const float4*)(xq + (size_t)warp * KEYD)
        : (const float4*)(ek + (size_t)(warp - B_) * KEYD);
    float ss = 0.f;
    #pragma unroll
    for (int i = 0; i < 6; i++) {
        float4 v = s4[lane + 32 * i];
        ss += v.x * v.x + v.y * v.y + v.z * v.z + v.w * v.w;
    }
    #pragma unroll
    for (int off = 16; off; off >>= 1) ss += __shfl_xor_sync(0xffffffffu, ss, off);
    if (lane == 0) {
        float inv = 1.0f / fmaxf(sqrtf(ss), 1e-12f);
        if (warp < B_) g_invq[warp] = inv; else g_invk[warp - B_] = inv;
    }
}

// tf32 tensor-core GEMM: C[B_,POOL] = (xq * eK^T) * invq[m] * invk[n]
#define BM 128
#define BN 64
#define BK 32
#define AST 136   // BK-major A tile stride  (bank = 8*tig+gid, conflict-free)
#define BST 72
__global__ __launch_bounds__(256) void gemm_tf32_kernel(const float* __restrict__ A,
                                                        const float* __restrict__ Bm,
                                                        float* __restrict__ C) {
    __shared__ uint32_t As[BK][AST];
    __shared__ uint32_t Bs[BK][BST];
    const int t    = threadIdx.x;
    const int lane = t & 31;
    const int wid  = t >> 5;
    const int gid  = lane >> 2;
    const int tig  = lane & 3;
    const int wm   = (wid >> 1) * 32;   // warp M offset (4 warps in M)
    const int wn   = (wid & 1) * 32;    // warp N offset (2 warps in N)
    const int m0   = blockIdx.y * BM;
    const int n0   = blockIdx.x * BN;

    // gmem load mapping (coalesced float4)
    const int ar = t >> 1;           // A row 0..127
    const int ac = (t & 1) * 16;     // A col base (floats): 0 or 16
    const int br = t >> 2;           // B row 0..63
    const int bcq = t & 3;           // B quad id

    const float4* Ag = (const float4*)(A  + (size_t)(m0 + ar) * KEYD + ac);
    const float4* Bg = (const float4*)(Bm + (size_t)(n0 + br) * KEYD + bcq * 4);

    float acc[2][4][4];
    #pragma unroll
    for (int i = 0; i < 2; i++)
        #pragma unroll
        for (int j = 0; j < 4; j++)
            #pragma unroll
            for (int v = 0; v < 4; v++) acc[i][j][v] = 0.f;

    float4 pa[4], pb[2];
    // prologue loads (k0 = 0)
    #pragma unroll
    for (int i = 0; i < 4; i++) pa[i] = Ag[i];
    pb[0] = Bg[0]; pb[1] = Bg[4];

    for (int k0 = 0; k0 < KEYD; k0 += BK) {
        __syncthreads();
        // ---- store A with component rotation (bank-conflict-free) ----
        #pragma unroll
        for (int i = 0; i < 4; i++) {
            float cm[4] = {pa[i].x, pa[i].y, pa[i].z, pa[i].w};
            #pragma unroll
            for (int s = 0; s < 4; s++) {
                int c = (s + 2 * (t & 1)) & 3;
                As[ac + 4 * i + c][ar] = f2tf(cm[c]);
            }
        }
        // ---- store B with component rotation ----
        #pragma unroll
        for (int half = 0; half < 2; half++) {
            float cm[4] = {pb[half].x, pb[half].y, pb[half].z, pb[half].w};
            #pragma unroll
            for (int s = 0; s < 4; s++) {
                int c = (s + bcq) & 3;
                Bs[half * 16 + bcq * 4 + c][br] = f2tf(cm[c]);
            }
        }
        __syncthreads();
        // ---- prefetch next tile ----
        if (k0 + BK < KEYD) {
            const float4* Ag2 = Ag + (k0 + BK) / 4;
            const float4* Bg2 = Bg + (k0 + BK) / 4;
            #pragma unroll
            for (int i = 0; i < 4; i++) pa[i] = Ag2[i];
            pb[0] = Bg2[0]; pb[1] = Bg2[4];
        }
        // ---- compute 4 k8-steps ----
        #pragma unroll
        for (int kk = 0; kk < BK; kk += 8) {
            uint32_t af[2][4], bf[4][2];
            #pragma unroll
            for (int mt = 0; mt < 2; mt++) {
                int mb = wm + mt * 16 + gid;
                af[mt][0] = As[kk + tig][mb];
                af[mt][1] = As[kk + tig][mb + 8];
                af[mt][2] = As[kk + tig + 4][mb];
                af[mt][3] = As[kk + tig + 4][mb + 8];
            }
            #pragma unroll
            for (int nt = 0; nt < 4; nt++) {
                int nb = wn + nt * 8 + gid;
                bf[nt][0] = Bs[kk + tig][nb];
                bf[nt][1] = Bs[kk + tig + 4][nb];
            }
            #pragma unroll
            for (int mt = 0; mt < 2; mt++)
                #pragma unroll
                for (int nt = 0; nt < 4; nt++)
                    mma_tf32(acc[mt][nt], af[mt], bf[nt]);
        }
    }

    // ---- epilogue: scale by inverse norms, store ----
    #pragma unroll
    for (int mt = 0; mt < 2; mt++) {
        int m = m0 + wm + mt * 16 + gid;
        float iq0 = g_invq[m], iq1 = g_invq[m + 8];
        #pragma unroll
        for (int nt = 0; nt < 4; nt++) {
            int n = n0 + wn + nt * 8 + 2 * tig;
            float ik0 = g_invk[n], ik1 = g_invk[n + 1];
            C[(size_t)m * POOL + n]           = acc[mt][nt][0] * iq0 * ik0;
            C[(size_t)m * POOL + n + 1]       = acc[mt][nt][1] * iq0 * ik1;
            C[(size_t)(m + 8) * POOL + n]     = acc[mt][nt][2] * iq1 * ik0;
            C[(size_t)(m + 8) * POOL + n + 1] = acc[mt][nt][3] * iq1 * ik1;
        }
    }
}

// warp-per-row: approx top-8 from tf32 C, exact fp32 re-check, final top-4 + counts
__global__ __launch_bounds__(256) void route_kernel(const float* __restrict__ C,
                                                    const float* __restrict__ xq,
                                                    const float* __restrict__ ek) {
    int row  = (blockIdx.x * blockDim.x + threadIdx.x) >> 5;
    int lane = threadIdx.x & 31;
    if (row >= B_) return;
    const float* crow = C + (size_t)row * POOL;
    float d[16];
    #pragma unroll
    for (int u = 0; u < 16; u++) d[u] = 1.0f - crow[u * 32 + lane];

    int cand[TOP8];
    #pragma unroll
    for (int k = 0; k < TOP8; k++) {
        float best = INFINITY; int bi = 0x7fffffff;
        #pragma unroll
        for (int u = 0; u < 16; u++) {
            int p = u * 32 + lane;
            if (d[u] < best || (d[u] == best && p < bi)) { best = d[u]; bi = p; }
        }
        #pragma unroll
        for (int off = 16; off; off >>= 1) {
            float ov = __shfl_xor_sync(0xffffffffu, best, off);
            int   oi = __shfl_xor_sync(0xffffffffu, bi, off);
            if (ov < best || (ov == best && oi < bi)) { best = ov; bi = oi; }
        }
        cand[k] = bi;
        if ((bi & 31) == lane) d[bi >> 5] = INFINITY;
    }

    // exact fp32 normalized distances for the 8 candidates
    const float4* q4 = (const float4*)(xq + (size_t)row * KEYD);
    float4 qv[6];
    #pragma unroll
    for (int i = 0; i < 6; i++) qv[i] = q4[lane + 32 * i];
    float iq = g_invq[row];
    float ex[TOP8];
    #pragma unroll
    for (int c = 0; c < TOP8; c++) {
        const float4* k4 = (const float4*)(ek + (size_t)cand[c] * KEYD);
        float s = 0.f;
        #pragma unroll
        for (int i = 0; i < 6; i++) {
            float4 kv = k4[lane + 32 * i];
            s += qv[i].x * kv.x + qv[i].y * kv.y + qv[i].z * kv.z + qv[i].w * kv.w;
        }
        #pragma unroll
        for (int off = 16; off; off >>= 1) s += __shfl_xor_sync(0xffffffffu, s, off);
        ex[c] = 1.0f - s * iq * g_invk[cand[c]];
    }

    // exact top-4 among the 8 (identical on all lanes), ties -> lowest pool idx
    bool used[TOP8];
    #pragma unroll
    for (int c = 0; c < TOP8; c++) used[c] = false;
    #pragma unroll
    for (int k = 0; k < TOPK; k++) {
        float best = INFINITY; int bi = 0x7fffffff; int slot = 0;
        #pragma unroll
        for (int c = 0; c < TOP8; c++) {
            if (!used[c] && (ex[c] < best || (ex[c] == best && cand[c] < bi))) {
                best = ex[c]; bi = cand[c]; slot = c;
            }
        }
        used[slot] = true;
        if (lane == 0) {
            g_idx[row * TOPK + k] = bi;
            atomicAdd(&g_cnt[bi], 1);
        }
    }
}

// column-sum partials of C
__global__ __launch_bounds__(256) void colpart_kernel(const float* __restrict__ C) {
    int col = blockIdx.x * 256 + threadIdx.x;
    int r0  = blockIdx.y * 128;
    float s = 0.f;
    #pragma unroll 4
    for (int r = 0; r < 128; r++) s += C[(size_t)(r0 + r) * POOL + col];
    g_partial[blockIdx.y * POOL + col] = s;
}

__global__ __launch_bounds__(512) void finish_kernel(float* __restrict__ out_loss,
                                                     float* __restrict__ out_counts) {
    int p = threadIdx.x;
    float colc = 0.f;
    #pragma unroll
    for (int g = 0; g < 16; g++) colc += g_partial[g * POOL + p];
    int c = g_cnt[p];
    out_counts[p] = (float)c;
    __shared__ float sm[512];
    sm[p] = colc * (float)c;
    __syncthreads();
    for (int s = 256; s > 0; s >>= 1) {
        if (p < s) sm[p] += sm[p + s];
        __syncthreads();
    }
    if (p == 0)
        *out_loss = 1.0f - sm[0] / ((float)B_ * (float)B_ * (float)TOPK);
}

// gather/concat Pk/Pv
__global__ __launch_bounds__(192) void gather_kernel(const float* __restrict__ e_p,
                                                     const float* __restrict__ g_p,
                                                     float* __restrict__ outPk,
                                                     float* __restrict__ outPv) {
    int b = blockIdx.y;
    int r = blockIdx.x;            // 0..19
    const float *sk, *sv;
    if (r < 16) {
        int p  = g_idx[b * TOPK + (r >> 2)];
        int rr = r & 3;
        sk = e_p + ((size_t)p * EPL + rr) * EMB;
        sv = e_p + ((size_t)p * EPL + 4 + rr) * EMB;
    } else {
        sk = g_p + (size_t)(r - 16) * EMB;
        sv = g_p + (size_t)(r - 16 + 4) * EMB;
    }
    size_t o = ((size_t)b * PK_ROWS + r) * EMB;
    int t = threadIdx.x;
    float4 vk = ((const float4*)sk)[t];
    float4 vv = ((const float4*)sv)[t];
    ((float4*)(outPk + o))[t] = vk;
    ((float4*)(outPv + o))[t] = vv;
}

// ---------------- launch ----------------
extern "C" void kernel_launch(void* const* d_in, const int* in_sizes, int n_in,
                              void* d_out, int out_size) {
    const float* x_querry = (const float*)d_in[0];
    const float* x_block  = (const float*)d_in[1];
    const float* e_k      = (const float*)d_in[2];
    const float* e_p      = (const float*)d_in[3];
    const float* g_p      = (const float*)d_in[4];
    (void)in_sizes; (void)n_in; (void)out_size;

    float* out = (float*)d_out;
    float* d_C = nullptr;
    cudaGetSymbolAddress((void**)&d_C, g_C);

    zero_cnt_kernel<<<1, POOL>>>();
    invnorm_kernel<<<(B_ + POOL) / 8, 256>>>(x_querry, e_k);
    gemm_tf32_kernel<<<dim3(POOL / BN, B_ / BM), 256>>>(x_querry, e_k, d_C);
    route_kernel<<<B_ / 8, 256>>>(d_C, x_querry, e_k);
    colpart_kernel<<<dim3(2, 16), 256>>>(d_C);
    finish_kernel<<<1, 512>>>(out + LOSS_OFF, out + CNT_OFF);
    gather_kernel<<<dim3(PK_ROWS, B_), 192>>>(e_p, g_p, out, out + PV_OFF);
    cudaMemcpyAsync(out + XB_OFF, x_block, (size_t)B_ * EMB * sizeof(float),
                    cudaMemcpyDeviceToDevice, 0);
}

// round 4
// speedup vs baseline: 1.3100x; 1.0347x over previous
#include <cuda_runtime.h>
#include <cstdint>
#include <math.h>

// ---------------- problem constants ----------------
#define B_    2048
#define POOL  512
#define TOPK  4
#define TOP8  8
#define EPL   8
#define GPL   8
#define EMB   768
#define KEYD  768

// output offsets (float32 elements)
#define PK_ROWS   20
#define PK_SZ     ((size_t)B_ * PK_ROWS * EMB)
#define PV_OFF    (PK_SZ)
#define LOSS_OFF  (2 * PK_SZ)
#define CNT_OFF   (LOSS_OFF + 1)
#define XB_OFF    (CNT_OFF + POOL)   // NOTE: odd offset -> only 4-byte aligned!

// ---------------- device scratch ----------------
__device__ float g_C[B_ * POOL];
__device__ float g_invq[B_];
__device__ float g_invk[POOL];
__device__ float g_sumq[KEYD];
__device__ float g_colsum[POOL];
__device__ int   g_idx[B_ * TOPK];
__device__ int   g_cnt[POOL];

// ---------------- helpers ----------------
__device__ __forceinline__ uint32_t f2tf(float f) {
    uint32_t r;
    asm("cvt.rna.tf32.f32 %0, %1;" : "=r"(r) : "f"(f));
    return r;
}
__device__ __forceinline__ void mma_tf32(float* c, const uint32_t* a, const uint32_t* b) {
    asm volatile(
        "mma.sync.aligned.m16n8k8.row.col.f32.tf32.tf32.f32 "
        "{%0,%1,%2,%3}, {%4,%5,%6,%7}, {%8,%9}, {%0,%1,%2,%3};"
        : "+f"(c[0]), "+f"(c[1]), "+f"(c[2]), "+f"(c[3])
        : "r"(a[0]), "r"(a[1]), "r"(a[2]), "r"(a[3]), "r"(b[0]), "r"(b[1]));
}

// ---------------- kernels ----------------

__global__ void zero_kernel() {
    int t = threadIdx.x;
    if (t < POOL) g_cnt[t] = 0;
    g_sumq[t] = 0.f;
}

// inverse L2 norms for x_querry rows (0..B_-1) and e_k rows (B_..B_+POOL-1)
__global__ __launch_bounds__(256) void invnorm_kernel(const float* __restrict__ xq,
                                                      const float* __restrict__ ek) {
    int warp = (blockIdx.x * 256 + threadIdx.x) >> 5;
    int lane = threadIdx.x & 31;
    if (warp >= B_ + POOL) return;
    const float4* s4 = (warp < B_)
        ? (const float4*)(xq + (size_t)warp * KEYD)
        : (const float4*)(ek + (size_t)(warp - B_) * KEYD);
    float ss = 0.f;
    #pragma unroll
    for (int i = 0; i < 6; i++) {
        float4 v = s4[lane + 32 * i];
        ss += v.x * v.x + v.y * v.y + v.z * v.z + v.w * v.w;
    }
    #pragma unroll
    for (int off = 16; off; off >>= 1) ss += __shfl_xor_sync(0xffffffffu, ss, off);
    if (lane == 0) {
        float inv = 1.0f / fmaxf(sqrtf(ss), 1e-12f);
        if (warp < B_) g_invq[warp] = inv; else g_invk[warp - B_] = inv;
    }
}

// tf32 GEMM: C[B_,POOL] = (xq * eK^T) * invq[m] * invk[n]
// BM=64 BN=64 BK=32, 256 threads (8 warps 2m x 4n, warp tile 32x16), double-buffered
#define BM 64
#define BN 64
#define BK 32
#define AST 72
__global__ __launch_bounds__(256) void gemm_tf32_kernel(const float* __restrict__ A,
                                                        const float* __restrict__ Bm,
                                                        float* __restrict__ C) {
    __shared__ uint32_t As[2][BK][AST];
    __shared__ uint32_t Bs[2][BK][AST];
    const int t    = threadIdx.x;
    const int lane = t & 31;
    const int wid  = t >> 5;
    const int gid  = lane >> 2;
    const int tig  = lane & 3;
    const int wm   = (wid >> 2) * 32;   // 0,32
    const int wn   = (wid & 3) * 16;    // 0,16,32,48
    const int m0   = blockIdx.y * BM;
    const int n0   = blockIdx.x * BN;

    // gmem mapping: 4 threads per row, 2 float4 each (full 32-float k-slab)
    const int arow = t >> 2;            // 0..63
    const int ac4  = (t & 3) * 2;       // float4 index base within 8
    const int rot  = t & 3;

    const float4* Ag = (const float4*)(A  + (size_t)(m0 + arow) * KEYD) + ac4;
    const float4* Bg = (const float4*)(Bm + (size_t)(n0 + arow) * KEYD) + ac4;

    float acc[2][2][4];
    #pragma unroll
    for (int i = 0; i < 2; i++)
        #pragma unroll
        for (int j = 0; j < 2; j++)
            #pragma unroll
            for (int v = 0; v < 4; v++) acc[i][j][v] = 0.f;

    float4 pa[2], pb[2];
    pa[0] = Ag[0]; pa[1] = Ag[1];
    pb[0] = Bg[0]; pb[1] = Bg[1];

    // store tile -> buf with component rotation (bank-conflict-free STS)
    #define STORE_TILE(buf_)                                                  \
        {                                                                     \
            _Pragma("unroll")                                                 \
            for (int i = 0; i < 2; i++) {                                     \
                float ca[4] = {pa[i].x, pa[i].y, pa[i].z, pa[i].w};           \
                float cb[4] = {pb[i].x, pb[i].y, pb[i].z, pb[i].w};           \
                _Pragma("unroll")                                             \
                for (int s = 0; s < 4; s++) {                                 \
                    int rc = (s + rot) & 3;                                   \
                    As[buf_][(ac4 + i) * 4 + rc][arow] = f2tf(ca[rc]);        \
                    Bs[buf_][(ac4 + i) * 4 + rc][arow] = f2tf(cb[rc]);        \
                }                                                             \
            }                                                                 \
        }

    STORE_TILE(0);
    __syncthreads();

    const int NIT = KEYD / BK;   // 24
    for (int it = 0; it < NIT; it++) {
        int buf = it & 1;
        if (it + 1 < NIT) {
            const float4* Ag2 = Ag + (it + 1) * (BK / 4);
            const float4* Bg2 = Bg + (it + 1) * (BK / 4);
            pa[0] = Ag2[0]; pa[1] = Ag2[1];
            pb[0] = Bg2[0]; pb[1] = Bg2[1];
        }
        #pragma unroll
        for (int kk = 0; kk < BK; kk += 8) {
            uint32_t af[2][4], bf[2][2];
            #pragma unroll
            for (int mt = 0; mt < 2; mt++) {
                int mb = wm + mt * 16 + gid;
                af[mt][0] = As[buf][kk + tig][mb];
                af[mt][1] = As[buf][kk + tig][mb + 8];
                af[mt][2] = As[buf][kk + tig + 4][mb];
                af[mt][3] = As[buf][kk + tig + 4][mb + 8];
            }
            #pragma unroll
            for (int nt = 0; nt < 2; nt++) {
                int nb = wn + nt * 8 + gid;
                bf[nt][0] = Bs[buf][kk + tig][nb];
                bf[nt][1] = Bs[buf][kk + tig + 4][nb];
            }
            #pragma unroll
            for (int mt = 0; mt < 2; mt++)
                #pragma unroll
                for (int nt = 0; nt < 2; nt++)
                    mma_tf32(acc[mt][nt], af[mt], bf[nt]);
        }
        if (it + 1 < NIT) STORE_TILE(buf ^ 1);
        __syncthreads();
    }

    #pragma unroll
    for (int mt = 0; mt < 2; mt++) {
        int m = m0 + wm + mt * 16 + gid;
        float iq0 = g_invq[m], iq1 = g_invq[m + 8];
        #pragma unroll
        for (int nt = 0; nt < 2; nt++) {
            int n = n0 + wn + nt * 8 + 2 * tig;
            float ik0 = g_invk[n], ik1 = g_invk[n + 1];
            C[(size_t)m * POOL + n]           = acc[mt][nt][0] * iq0 * ik0;
            C[(size_t)m * POOL + n + 1]       = acc[mt][nt][1] * iq0 * ik1;
            C[(size_t)(m + 8) * POOL + n]     = acc[mt][nt][2] * iq1 * ik0;
            C[(size_t)(m + 8) * POOL + n + 1] = acc[mt][nt][3] * iq1 * ik1;
        }
    }
}

// sum_q[j] = sum_b xq[b][j] * invq[b]   (grid 64, 32 rows/block)
__global__ __launch_bounds__(256) void sumq_kernel(const float* __restrict__ xq) {
    int r0 = blockIdx.x * 32;
    int t = threadIdx.x;
    float s0 = 0.f, s1 = 0.f, s2 = 0.f;
    for (int r = 0; r < 32; r++) {
        float iq = g_invq[r0 + r];
        const float* xr = xq + (size_t)(r0 + r) * KEYD;
        s0 += xr[t] * iq;
        s1 += xr[t + 256] * iq;
        s2 += xr[t + 512] * iq;
    }
    atomicAdd(&g_sumq[t], s0);
    atomicAdd(&g_sumq[t + 256], s1);
    atomicAdd(&g_sumq[t + 512], s2);
}

// colsum[p] = invk[p] * dot(e_k[p], sum_q)   (warp per pool entry)
__global__ __launch_bounds__(256) void colsum_kernel(const float* __restrict__ ek) {
    int w = threadIdx.x >> 5, lane = threadIdx.x & 31;
    int p = blockIdx.x * 8 + w;
    const float4* k4 = (const float4*)(ek + (size_t)p * KEYD);
    const float4* s4 = (const float4*)g_sumq;
    float s = 0.f;
    #pragma unroll
    for (int i = 0; i < 6; i++) {
        float4 kv = k4[lane + 32 * i];
        float4 sv = s4[lane + 32 * i];
        s += kv.x * sv.x + kv.y * sv.y + kv.z * sv.z + kv.w * sv.w;
    }
    #pragma unroll
    for (int off = 16; off; off >>= 1) s += __shfl_xor_sync(0xffffffffu, s, off);
    if (lane == 0) g_colsum[p] = s * g_invk[p];
}

// block per row: warp0 approx top-8 from tf32 C; 4 warps exact-recheck 2 cands each
__global__ __launch_bounds__(128) void route_kernel(const float* __restrict__ C,
                                                    const float* __restrict__ xq,
                                                    const float* __restrict__ ek) {
    int row  = blockIdx.x;
    int t    = threadIdx.x;
    int lane = t & 31;
    int w    = t >> 5;
    __shared__ int   s_cand[TOP8];
    __shared__ float s_ex[TOP8];

    if (w == 0) {
        const float* crow = C + (size_t)row * POOL;
        float d[16];
        #pragma unroll
        for (int u = 0; u < 16; u++) d[u] = 1.0f - crow[u * 32 + lane];
        #pragma unroll
        for (int k = 0; k < TOP8; k++) {
            float best = INFINITY; int bi = 0x7fffffff;
            #pragma unroll
            for (int u = 0; u < 16; u++) {
                int p = u * 32 + lane;
                if (d[u] < best || (d[u] == best && p < bi)) { best = d[u]; bi = p; }
            }
            #pragma unroll
            for (int off = 16; off; off >>= 1) {
                float ov = __shfl_xor_sync(0xffffffffu, best, off);
                int   oi = __shfl_xor_sync(0xffffffffu, bi, off);
                if (ov < best || (ov == best && oi < bi)) { best = ov; bi = oi; }
            }
            if (lane == 0) s_cand[k] = bi;
            int ul = bi >> 5, ll = bi & 31;
            #pragma unroll
            for (int u = 0; u < 16; u++)
                if (u == ul && ll == lane) d[u] = INFINITY;   // no dynamic reg index
        }
    }
    __syncthreads();

    // exact fp32 recheck: warp w handles candidates 2w, 2w+1
    const float4* q4 = (const float4*)(xq + (size_t)row * KEYD);
    float4 qv[6];
    #pragma unroll
    for (int i = 0; i < 6; i++) qv[i] = q4[lane + 32 * i];
    float iq = g_invq[row];
    #pragma unroll
    for (int cc = 0; cc < 2; cc++) {
        int ci = w * 2 + cc;
        int p  = s_cand[ci];
        const float4* k4 = (const float4*)(ek + (size_t)p * KEYD);
        float s = 0.f;
        #pragma unroll
        for (int i = 0; i < 6; i++) {
            float4 kv = k4[lane + 32 * i];
            s += qv[i].x * kv.x + qv[i].y * kv.y + qv[i].z * kv.z + qv[i].w * kv.w;
        }
        #pragma unroll
        for (int off = 16; off; off >>= 1) s += __shfl_xor_sync(0xffffffffu, s, off);
        if (lane == 0) s_ex[ci] = 1.0f - s * iq * g_invk[p];
    }
    __syncthreads();

    if (t == 0) {
        bool used[TOP8];
        #pragma unroll
        for (int c = 0; c < TOP8; c++) used[c] = false;
        #pragma unroll
        for (int k = 0; k < TOPK; k++) {
            float best = INFINITY; int bi = 0x7fffffff; int slot = 0;
            #pragma unroll
            for (int c = 0; c < TOP8; c++) {
                if (!used[c] && (s_ex[c] < best || (s_ex[c] == best && s_cand[c] < bi))) {
                    best = s_ex[c]; bi = s_cand[c]; slot = c;
                }
            }
            used[slot] = true;
            g_idx[row * TOPK + k] = bi;
            atomicAdd(&g_cnt[bi], 1);
        }
    }
}

__global__ __launch_bounds__(512) void finish_kernel(float* __restrict__ out_loss,
                                                     float* __restrict__ out_counts) {
    int p = threadIdx.x;
    int c = g_cnt[p];
    out_counts[p] = (float)c;
    __shared__ float sm[512];
    sm[p] = g_colsum[p] * (float)c;
    __syncthreads();
    for (int s = 256; s > 0; s >>= 1) {
        if (p < s) sm[p] += sm[p + s];
        __syncthreads();
    }
    if (p == 0)
        *out_loss = 1.0f - sm[0] / ((float)B_ * (float)B_ * (float)TOPK);
}

// gather/concat Pk/Pv + x_block passthrough (r==20).
// XB_OFF is only 4-byte aligned -> passthrough uses float4 LOADS but scalar STORES.
__global__ __launch_bounds__(192) void gather_kernel(const float* __restrict__ e_p,
                                                     const float* __restrict__ g_p,
                                                     const float* __restrict__ xb,
                                                     float* __restrict__ out) {
    int b = blockIdx.y;
    int r = blockIdx.x;            // 0..20
    int t = threadIdx.x;
    if (r == 20) {
        float4 v = ((const float4*)(xb + (size_t)b * EMB))[t];  // src is 16B-aligned
        float* d = out + XB_OFF + (size_t)b * EMB + 4 * t;      // dst only 4B-aligned
        d[0] = v.x; d[1] = v.y; d[2] = v.z; d[3] = v.w;
        return;
    }
    const float *sk, *sv;
    if (r < 16) {
        int p  = g_idx[b * TOPK + (r >> 2)];
        int rr = r & 3;
        sk = e_p + ((size_t)p * EPL + rr) * EMB;
        sv = e_p + ((size_t)p * EPL + 4 + rr) * EMB;
    } else {
        sk = g_p + (size_t)(r - 16) * EMB;
        sv = g_p + (size_t)(r - 16 + 4) * EMB;
    }
    size_t o = ((size_t)b * PK_ROWS + r) * EMB;
    float4 vk = ((const float4*)sk)[t];
    float4 vv = ((const float4*)sv)[t];
    ((float4*)(out + o))[t] = vk;
    ((float4*)(out + PV_OFF + o))[t] = vv;
}

// ---------------- launch ----------------
extern "C" void kernel_launch(void* const* d_in, const int* in_sizes, int n_in,
                              void* d_out, int out_size) {
    const float* x_querry = (const float*)d_in[0];
    const float* x_block  = (const float*)d_in[1];
    const float* e_k      = (const float*)d_in[2];
    const float* e_p      = (const float*)d_in[3];
    const float* g_p      = (const float*)d_in[4];
    (void)in_sizes; (void)n_in; (void)out_size;

    float* out = (float*)d_out;
    float* d_C = nullptr;
    cudaGetSymbolAddress((void**)&d_C, g_C);

    zero_kernel<<<1, KEYD>>>();
    invnorm_kernel<<<(B_ + POOL) / 8, 256>>>(x_querry, e_k);
    gemm_tf32_kernel<<<dim3(POOL / BN, B_ / BM), 256>>>(x_querry, e_k, d_C);
    sumq_kernel<<<B_ / 32, 256>>>(x_querry);
    colsum_kernel<<<POOL / 8, 256>>>(e_k);
    route_kernel<<<B_, 128>>>(d_C, x_querry, e_k);
    finish_kernel<<<1, 512>>>(out + LOSS_OFF, out + CNT_OFF);
    gather_kernel<<<dim3(PK_ROWS + 1, B_), 192>>>(e_p, g_p, x_block, out);
}